// round 15
// baseline (speedup 1.0000x reference)
#include <cuda_runtime.h>
#include <cuda_bf16.h>
#include <cstdint>

#define NB 64
#define TT 512
#define II 512
#define HH 1024
#define OO 512
#define NT (NB*TT)
#define NHh (NB*HH)

__device__ float g_bufA[TT*NB*HH];
__device__ float g_bufB[TT*NB*HH];
__device__ float g_hx0[HH*NB];
__device__ float g_hx1[HH*NB];
__device__ unsigned g_gflag[32*32];
__device__ unsigned g_done[2*32];
__device__ unsigned g_g1slab[4*32];
__device__ unsigned g_g3slab[4*32];
__device__ unsigned g_g4slab[4*32];
__device__ __nv_bfloat16 g_dHi[NT*II],  g_dLo[NT*II];
__device__ __nv_bfloat16 g_aHi[NT*HH],  g_aLo[NT*HH];
__device__ __nv_bfloat16 g_oHi[NT*OO],  g_oLo[NT*OO];
__device__ __nv_bfloat16 g_o2Hi[NT*OO], g_o2Lo[NT*OO];
__device__ __nv_bfloat16 g_WiH[HH*II],  g_WiL[HH*II];
__device__ __nv_bfloat16 g_WoH[OO*HH],  g_WoL[OO*HH];
__device__ __nv_bfloat16 g_WtH[OO*OO],  g_WtL[OO*OO];
__device__ __nv_bfloat16 g_Wi2H[HH*OO], g_Wi2L[HH*OO];
__device__ __nv_bfloat16 g_Wo2H[OO*HH], g_Wo2L[OO*HH];

__device__ __forceinline__ unsigned long long dup2(float a) {
    unsigned long long r; asm("mov.b64 %0, {%1, %1};" : "=l"(r) : "f"(a)); return r;
}
__device__ __forceinline__ void fma2(unsigned long long& c, unsigned long long a,
                                     unsigned long long b) {
    asm("fma.rn.f32x2 %0, %1, %2, %0;" : "+l"(c) : "l"(a), "l"(b));
}
__device__ __forceinline__ unsigned ld_acq(const unsigned* p) {
    unsigned v;
    asm volatile("ld.acquire.gpu.global.u32 %0, [%1];" : "=r"(v) : "l"(p));
    return v;
}
__device__ __forceinline__ void red_rel(unsigned* p, unsigned v) {
    asm volatile("red.add.release.gpu.global.u32 [%0], %1;" :: "l"(p), "r"(v));
}
__device__ __forceinline__ float retanh(float x) {
    float xm = fmaxf(x, 0.0f);
    float e;
    asm("ex2.approx.f32 %0, %1;" : "=f"(e) : "f"(xm * -2.885390082f));
    return __fdividef(1.0f - e, 1.0f + e);
}
__device__ __forceinline__ uint32_t smem_u32(const void* p) {
    uint32_t a;
    asm("{ .reg .u64 t; cvta.to.shared.u64 t, %1; cvt.u32.u64 %0, t; }"
        : "=r"(a) : "l"(p));
    return a;
}
__device__ __forceinline__ void ldmx4(uint32_t* r, uint32_t addr) {
    asm volatile("ldmatrix.sync.aligned.m8n8.x4.shared.b16 {%0,%1,%2,%3}, [%4];"
                 : "=r"(r[0]), "=r"(r[1]), "=r"(r[2]), "=r"(r[3]) : "r"(addr));
}
__device__ __forceinline__ void mma16816(float* c, const uint32_t* a,
                                         uint32_t b0, uint32_t b1) {
    asm volatile(
        "mma.sync.aligned.m16n8k16.row.col.f32.bf16.bf16.f32 "
        "{%0,%1,%2,%3}, {%4,%5,%6,%7}, {%8,%9}, {%0,%1,%2,%3};"
        : "+f"(c[0]), "+f"(c[1]), "+f"(c[2]), "+f"(c[3])
        : "r"(a[0]), "r"(a[1]), "r"(a[2]), "r"(a[3]), "r"(b0), "r"(b1));
}
__device__ __forceinline__ void cpa16(uint32_t dst, const void* src) {
    asm volatile("cp.async.cg.shared.global [%0], [%1], 16;"
                 :: "r"(dst), "l"(src) : "memory");
}
#define CPA_COMMIT asm volatile("cp.async.commit_group;" ::: "memory")
#define CPA_WAIT1  asm volatile("cp.async.wait_group 1;" ::: "memory")
#define CPA_WAIT0  asm volatile("cp.async.wait_group 0;" ::: "memory")

// ---------- 512-thread HMMA tile: BM=128, BN=128, warp tile 32x32, split-bf16 --
__device__ void hgemm512(
    const __nv_bfloat16* __restrict__ Ahi, const __nv_bfloat16* __restrict__ Alo,
    const __nv_bfloat16* __restrict__ Bhi, const __nv_bfloat16* __restrict__ Blo,
    const float* __restrict__ b1, const float* __restrict__ b2,
    float* __restrict__ C, __nv_bfloat16* __restrict__ hiO,
    __nv_bfloat16* __restrict__ loO,
    int K, int Nc, int m0, int j0, int D1, int D2, int act, int omode,
    char* sm)
{
    __nv_bfloat16* smA = (__nv_bfloat16*)sm;            // [2][128*40]
    __nv_bfloat16* smB = (__nv_bfloat16*)(sm + 20480);  // [2][128*40]
    const int tid = threadIdx.x, lane = tid & 31, wid = tid >> 5;
    const int wm = wid & 3, wn = wid >> 2;              // 4x4 warps
    const int crow = tid >> 2, cq = (tid & 3) * 8;      // copy map
    const int KC = K / 32, NCH = 3 * KC;

    float acc[2][4][4];
#pragma unroll
    for (int i = 0; i < 2; i++)
#pragma unroll
        for (int j = 0; j < 4; j++)
#pragma unroll
            for (int q = 0; q < 4; q++) acc[i][j][q] = 0.0f;

    auto copy_chunk = [&](int c, int b) {
        const int p = c / KC;
        const int kt = (c - p * KC) * 32;
        const __nv_bfloat16* pA = (p == 2) ? Alo : Ahi;
        const __nv_bfloat16* pB = (p == 1) ? Blo : Bhi;
        cpa16(smem_u32(smA + b * 5120 + crow * 40 + cq),
              pA + (size_t)(m0 + crow) * K + kt + cq);
        cpa16(smem_u32(smB + b * 5120 + crow * 40 + cq),
              pB + (size_t)(j0 + crow) * K + kt + cq);
    };

    copy_chunk(0, 0); CPA_COMMIT;
    copy_chunk(1, 1); CPA_COMMIT;

    for (int c = 0; c < NCH; c++) {
        if (c + 1 < NCH) { CPA_WAIT1; } else { CPA_WAIT0; }
        __syncthreads();
        const int cur = c & 1;
        const uint32_t baseA = smem_u32(smA + cur * 5120);
        const uint32_t baseB = smem_u32(smB + cur * 5120);
#pragma unroll
        for (int kk = 0; kk < 2; kk++) {
            uint32_t aF[2][4], bF[2][4];
#pragma unroll
            for (int mt = 0; mt < 2; mt++)
                ldmx4(aF[mt], baseA +
                      ((wm * 32 + mt * 16 + (lane & 15)) * 40 + kk * 16 + (lane >> 4) * 8) * 2);
#pragma unroll
            for (int np = 0; np < 2; np++)
                ldmx4(bF[np], baseB +
                      ((wn * 32 + np * 16 + (lane & 15)) * 40 + kk * 16 + (lane >> 4) * 8) * 2);
#pragma unroll
            for (int mt = 0; mt < 2; mt++)
#pragma unroll
                for (int np = 0; np < 2; np++) {
                    mma16816(acc[mt][2 * np + 0], aF[mt], bF[np][0], bF[np][2]);
                    mma16816(acc[mt][2 * np + 1], aF[mt], bF[np][1], bF[np][3]);
                }
        }
        __syncthreads();
        if (c + 2 < NCH) { copy_chunk(c + 2, cur); CPA_COMMIT; }
    }

#pragma unroll
    for (int mt = 0; mt < 2; mt++) {
        const int rbase = m0 + wm * 32 + mt * 16 + (lane >> 2);
#pragma unroll
        for (int half = 0; half < 2; half++) {
            const int rm = rbase + half * 8;
            const int orow = (rm % D1) * D2 + rm / D1;
#pragma unroll
            for (int nt = 0; nt < 4; nt++) {
                const int cn = j0 + wn * 32 + nt * 8 + (lane & 3) * 2;
                float bb0 = b1[cn], bb1 = b1[cn + 1];
                if (b2) { bb0 += b2[cn]; bb1 += b2[cn + 1]; }
                float x = acc[mt][nt][2 * half + 0] + bb0;
                float y = acc[mt][nt][2 * half + 1] + bb1;
                if (act) { x = retanh(x); y = retanh(y); }
                const size_t oidx = (size_t)orow * Nc + cn;
                if (omode == 0) {
                    float2 v; v.x = x; v.y = y;
                    *(float2*)(C + oidx) = v;
                } else {
                    __nv_bfloat16 hx = __float2bfloat16(x);
                    __nv_bfloat16 hy = __float2bfloat16(y);
                    __nv_bfloat16 lx = __float2bfloat16(x - __bfloat162float(hx));
                    __nv_bfloat16 ly = __float2bfloat16(y - __bfloat162float(hy));
                    *(__nv_bfloat162*)(hiO + oidx) = __nv_bfloat162(hx, hy);
                    *(__nv_bfloat162*)(loO + oidx) = __nv_bfloat162(lx, ly);
                }
            }
        }
    }
}

// ---------- recurrence body (benched R13 math + g_done + optional G1 gate) ----
__device__ void recur_body(float* __restrict__ buf, const float* __restrict__ Wh,
                           int rgate, float* smem)
{
    float* Whs = smem;
    unsigned long long* redU = (unsigned long long*)(smem + 16384);
    const int tid  = threadIdx.x;
    const int bidb = blockIdx.x >> 6;
    const int bidh = blockIdx.x & 63;
    const int nb0  = bidb * 32;
    const int c0   = bidh * 16;
    {
        const int cl = tid & 15;
        const int kb = (tid >> 4) * 32;
        const float* wrow = Wh + (size_t)(c0 + cl) * HH + kb;
#pragma unroll
        for (int kk = 0; kk < 32; kk++) Whs[(kb + kk) * 16 + cl] = wrow[kk];
    }
    __syncthreads();
    const int wid  = tid >> 5;
    const int lane = tid & 31;
    const int k0   = wid * 64;
    const int cR   = lane & 15;
    const int nR   = 2 * wid + (lane >> 4);
    const float* redF = (const float*)redU;
    const unsigned* wf = &g_gflag[(bidb * 16 + wid) * 32];
    unsigned* pf = &g_gflag[(bidb * 16 + (bidh >> 2)) * 32];

    for (int t = 0; t < TT; t++) {
        if (rgate && (t & 127) == 0) {
            if (tid == 0)
                while (ld_acq(&g_g1slab[(t >> 7) * 32]) < 512u) __nanosleep(40);
            __syncthreads();
        }
        const float* hp = ((t & 1) ? g_hx1 : g_hx0) + (size_t)k0 * NB + nb0 + lane;
        float*       hn = ((t & 1) ? g_hx0 : g_hx1);
        const size_t oidx = (size_t)t * NHh + (size_t)(nb0 + nR) * HH + (c0 + cR);
        float* outp = buf + oidx;
        const float x_pre = __ldcg(outp);
        {
            const unsigned tgt = 4u * (unsigned)t;
            while (ld_acq(wf) < tgt) __nanosleep(20);
        }
        unsigned long long acc[8];
#pragma unroll
        for (int j = 0; j < 8; j++) acc[j] = 0ull;
        float hbuf[3][8];
#pragma unroll
        for (int j = 0; j < 8; j++) hbuf[0][j] = __ldcg(hp + (size_t)j * NB);
#pragma unroll
        for (int j = 0; j < 8; j++) hbuf[1][j] = __ldcg(hp + (size_t)(8 + j) * NB);
#pragma unroll
        for (int g = 0; g < 8; g++) {
            if (g + 2 < 8) {
#pragma unroll
                for (int j = 0; j < 8; j++)
                    hbuf[(g + 2) % 3][j] = __ldcg(hp + (size_t)((g + 2) * 8 + j) * NB);
            }
#pragma unroll
            for (int j = 0; j < 8; j++) {
                const unsigned long long ad = dup2(hbuf[g % 3][j]);
                const float* wk = &Whs[(k0 + g * 8 + j) * 16];
                ulonglong2 w0 = *(const ulonglong2*)(wk + 0);
                ulonglong2 w1 = *(const ulonglong2*)(wk + 4);
                ulonglong2 w2 = *(const ulonglong2*)(wk + 8);
                ulonglong2 w3 = *(const ulonglong2*)(wk + 12);
                fma2(acc[0], ad, w0.x); fma2(acc[1], ad, w0.y);
                fma2(acc[2], ad, w1.x); fma2(acc[3], ad, w1.y);
                fma2(acc[4], ad, w2.x); fma2(acc[5], ad, w2.y);
                fma2(acc[6], ad, w3.x); fma2(acc[7], ad, w3.y);
            }
        }
        {
            unsigned long long* rp = &redU[(size_t)(wid * 32 + lane) * 9];
#pragma unroll
            for (int j = 0; j < 8; j++) rp[j] = acc[j];
        }
        __syncthreads();
        float s = 0.0f;
#pragma unroll
        for (int w = 0; w < 16; w++) s += redF[(w * 32 + nR) * 18 + cR];
        const float v = retanh(s + x_pre);
        *outp = v;
        {
            __nv_bfloat16 hv = __float2bfloat16(v);
            g_aHi[oidx] = hv;
            g_aLo[oidx] = __float2bfloat16(v - __bfloat162float(hv));
        }
        hn[(size_t)(c0 + cR) * NB + nb0 + nR] = v;
        __syncthreads();
        if (tid == 0) {
            red_rel(pf, 1u);
            red_rel(&g_done[bidb * 32], 1u);
        }
    }
}

#define RSMEM ((16384 + 9216) * 4)   // 100 KB (gemm roles use 80 KB of it)

// ---------- MEGA-A: recur_v + G1 + G3 + G4 + G5 -------------------------------
__global__ __launch_bounds__(512, 2) void mega_a(
    const float* Wh, const float* bi, const float* bh, const float* bo,
    const float* bt, const float* bi2, const float* bh2)
{
    extern __shared__ float smemf[];
    char* sm = (char*)smemf;
    const int tid = threadIdx.x;
    int bid = blockIdx.x;
    if (bid < 128) { recur_body(g_bufA, Wh, 1, smemf); return; }
    bid -= 128;
    if (bid < 2048) {   // G1: inp_v = data@Wi^T+(bi+bh) -> fp32 [T,N,H]
        const int y = bid >> 3, x = bid & 7;
        hgemm512(g_dHi, g_dLo, g_WiH, g_WiL, bi, bh, g_bufA, 0, 0,
                 II, HH, y * 128, x * 128, TT, NB, 0, 0, sm);
        __syncthreads();
        // t-slab of linear m-block y*128 is (y & 3)  [t = rm % 512]
        if (tid == 0) red_rel(&g_g1slab[(y & 3) * 32], 1u);
        return;
    }
    bid -= 2048;
    if (bid < 1024) {   // G3: out_v = hs_v@Wo^T+bo -> bf16 split [N,T,O]
        const int y = bid >> 2, x = bid & 3;
        if (tid == 0) {
            const unsigned tgt = 64u * (unsigned)(2 * y + 2);
            while (ld_acq(&g_done[0])  < tgt) __nanosleep(100);
            while (ld_acq(&g_done[32]) < tgt) __nanosleep(100);
        }
        __syncthreads();
        hgemm512(g_aHi, g_aLo, g_WoH, g_WoL, bo, 0, 0, g_oHi, g_oLo,
                 HH, OO, y * 128, x * 128, NB, TT, 0, 1, sm);
        __syncthreads();
        // output t-slab of m-block y*128 is y>>6  [t = rm / 64]
        if (tid == 0) red_rel(&g_g3slab[(y >> 6) * 32], 1u);
        return;
    }
    bid -= 1024;
    if (bid < 1024) {   // G4: out_t = retanh(out_v@Wt^T+bt) -> bf16 split
        const int tb = bid >> 8, rest = bid & 255;
        const int n = rest >> 2, x = rest & 3;
        if (tid == 0)
            while (ld_acq(&g_g3slab[tb * 32]) < 256u) __nanosleep(100);
        __syncthreads();
        hgemm512(g_oHi, g_oLo, g_WtH, g_WtL, bt, 0, 0, g_o2Hi, g_o2Lo,
                 OO, OO, n * 512 + tb * 128, x * 128, NT, 1, 1, 1, sm);
        __syncthreads();
        if (tid == 0) red_rel(&g_g4slab[tb * 32], 1u);
        return;
    }
    bid -= 1024;
    {                   // G5: inp_m = out_t@Wi2^T+(bi2+bh2) -> fp32 [T,N,H]
        const int tb = bid >> 9, rest = bid & 511;
        const int n = rest >> 3, x = rest & 7;
        if (tid == 0)
            while (ld_acq(&g_g4slab[tb * 32]) < 256u) __nanosleep(100);
        __syncthreads();
        hgemm512(g_o2Hi, g_o2Lo, g_Wi2H, g_Wi2L, bi2, bh2, g_bufB, 0, 0,
                 OO, HH, n * 512 + tb * 128, x * 128, TT, NB, 0, 0, sm);
    }
}

// ---------- MEGA-B: recur_m + G7 ----------------------------------------------
__global__ __launch_bounds__(512, 2) void mega_b(
    const float* Wh2, const float* bo2, float* out)
{
    extern __shared__ float smemf[];
    char* sm = (char*)smemf;
    const int tid = threadIdx.x;
    int bid = blockIdx.x;
    if (bid < 128) { recur_body(g_bufB, Wh2, 0, smemf); return; }
    bid -= 128;
    {                   // G7: out_m = hs_m@Wo2^T+bo2 -> fp32 [N,T,O]
        const int y = bid >> 2, x = bid & 3;
        if (tid == 0) {
            const unsigned tgt = 64u * (unsigned)(2 * y + 2);
            while (ld_acq(&g_done[0])  < tgt) __nanosleep(100);
            while (ld_acq(&g_done[32]) < tgt) __nanosleep(100);
        }
        __syncthreads();
        hgemm512(g_aHi, g_aLo, g_Wo2H, g_Wo2L, bo2, 0, out, 0, 0,
                 HH, OO, y * 128, x * 128, NB, TT, 0, 0, sm);
    }
}

// ---------- converts + helpers -------------------------------------------------
__global__ __launch_bounds__(256) void cvt_split(
    const float* __restrict__ x, __nv_bfloat16* __restrict__ hi,
    __nv_bfloat16* __restrict__ lo, int n4)
{
    const int i = blockIdx.x * 256 + threadIdx.x;
    if (i >= n4) return;
    const float4 v = ((const float4*)x)[i];
    __nv_bfloat16 h0 = __float2bfloat16(v.x), h1 = __float2bfloat16(v.y);
    __nv_bfloat16 h2 = __float2bfloat16(v.z), h3 = __float2bfloat16(v.w);
    __nv_bfloat16 l0 = __float2bfloat16(v.x - __bfloat162float(h0));
    __nv_bfloat16 l1 = __float2bfloat16(v.y - __bfloat162float(h1));
    __nv_bfloat16 l2 = __float2bfloat16(v.z - __bfloat162float(h2));
    __nv_bfloat16 l3 = __float2bfloat16(v.w - __bfloat162float(h3));
    ((__nv_bfloat162*)hi)[2 * i]     = __nv_bfloat162(h0, h1);
    ((__nv_bfloat162*)hi)[2 * i + 1] = __nv_bfloat162(h2, h3);
    ((__nv_bfloat162*)lo)[2 * i]     = __nv_bfloat162(l0, l1);
    ((__nv_bfloat162*)lo)[2 * i + 1] = __nv_bfloat162(l2, l3);
}
__global__ __launch_bounds__(512) void transpose_h0(
    const float* __restrict__ h0, float* __restrict__ hx)
{
    const int idx = blockIdx.x * 512 + threadIdx.x;
    hx[idx] = h0[(size_t)(idx & 63) * HH + (idx >> 6)];
}
__global__ __launch_bounds__(1024) void reset_flags_kernel() {
    const int i = threadIdx.x;
    g_gflag[i] = 0u;
    if (i < 64)  g_done[i] = 0u;
    if (i < 128) { g_g1slab[i] = 0u; g_g3slab[i] = 0u; g_g4slab[i] = 0u; }
}

// ---------- launcher ------------------------------------------------------------
static void cvt(const float* x, __nv_bfloat16* hi, __nv_bfloat16* lo, int n) {
    cvt_split<<<(n / 4 + 255) / 256, 256>>>(x, hi, lo, n / 4);
}

extern "C" void kernel_launch(void* const* d_in, const int* in_sizes, int n_in,
                              void* d_out, int out_size)
{
    const float* data = (const float*)d_in[0];
    const float* h0_v = (const float*)d_in[1];
    const float* h0_m = (const float*)d_in[2];
    const float* Wi   = (const float*)d_in[3];
    const float* bi   = (const float*)d_in[4];
    const float* Wh   = (const float*)d_in[5];
    const float* bh   = (const float*)d_in[6];
    const float* Wo   = (const float*)d_in[7];
    const float* bo   = (const float*)d_in[8];
    const float* Wt   = (const float*)d_in[9];
    const float* bt   = (const float*)d_in[10];
    const float* Wi2  = (const float*)d_in[11];
    const float* bi2  = (const float*)d_in[12];
    const float* Wh2  = (const float*)d_in[13];
    const float* bh2  = (const float*)d_in[14];
    const float* Wo2  = (const float*)d_in[15];
    const float* bo2  = (const float*)d_in[16];
    float* out = (float*)d_out;

    float *hx0;
    cudaGetSymbolAddress((void**)&hx0, g_hx0);
    __nv_bfloat16 *dH,*dL,*WiH,*WiL,*WoH,*WoL,*WtH,*WtL,*Wi2H,*Wi2L,*Wo2H,*Wo2L;
    cudaGetSymbolAddress((void**)&dH, g_dHi);    cudaGetSymbolAddress((void**)&dL, g_dLo);
    cudaGetSymbolAddress((void**)&WiH, g_WiH);   cudaGetSymbolAddress((void**)&WiL, g_WiL);
    cudaGetSymbolAddress((void**)&WoH, g_WoH);   cudaGetSymbolAddress((void**)&WoL, g_WoL);
    cudaGetSymbolAddress((void**)&WtH, g_WtH);   cudaGetSymbolAddress((void**)&WtL, g_WtL);
    cudaGetSymbolAddress((void**)&Wi2H, g_Wi2H); cudaGetSymbolAddress((void**)&Wi2L, g_Wi2L);
    cudaGetSymbolAddress((void**)&Wo2H, g_Wo2H); cudaGetSymbolAddress((void**)&Wo2L, g_Wo2L);

    cudaFuncSetAttribute(mega_a, cudaFuncAttributeMaxDynamicSharedMemorySize, RSMEM);
    cudaFuncSetAttribute(mega_b, cudaFuncAttributeMaxDynamicSharedMemorySize, RSMEM);

    cvt(Wi,  WiH,  WiL,  HH * II);
    cvt(Wo,  WoH,  WoL,  OO * HH);
    cvt(Wt,  WtH,  WtL,  OO * OO);
    cvt(Wi2, Wi2H, Wi2L, HH * OO);
    cvt(Wo2, Wo2H, Wo2L, OO * HH);
    cvt(data, dH, dL, NT * II);

    transpose_h0<<<128, 512>>>(h0_v, hx0);
    reset_flags_kernel<<<1, 1024>>>();
    mega_a<<<128 + 2048 + 1024 + 1024 + 2048, 512, RSMEM>>>(
        Wh, bi, bh, bo, bt, bi2, bh2);

    transpose_h0<<<128, 512>>>(h0_m, hx0);
    reset_flags_kernel<<<1, 1024>>>();
    mega_b<<<128 + 1024, 512, RSMEM>>>(Wh2, bo2, out);
}

// round 16
// speedup vs baseline: 1.4659x; 1.4659x over previous
#include <cuda_runtime.h>
#include <cuda_bf16.h>
#include <cstdint>

#define NB 64
#define TT 512
#define II 512
#define HH 1024
#define OO 512
#define NT (NB*TT)
#define NHh (NB*HH)

__device__ float g_bufA[TT*NB*HH];
__device__ float g_bufB[TT*NB*HH];
__device__ unsigned g_gflag[32*32];
__device__ __nv_bfloat16 g_h0H[NB*HH], g_h0L[NB*HH];
__device__ __nv_bfloat16 g_dHi[NT*II],  g_dLo[NT*II];
__device__ __nv_bfloat16 g_aHi[NT*HH],  g_aLo[NT*HH];
__device__ __nv_bfloat16 g_oHi[NT*OO],  g_oLo[NT*OO];
__device__ __nv_bfloat16 g_o2Hi[NT*OO], g_o2Lo[NT*OO];
__device__ __nv_bfloat16 g_WiH[HH*II],  g_WiL[HH*II];
__device__ __nv_bfloat16 g_WoH[OO*HH],  g_WoL[OO*HH];
__device__ __nv_bfloat16 g_WtH[OO*OO],  g_WtL[OO*OO];
__device__ __nv_bfloat16 g_Wi2H[HH*OO], g_Wi2L[HH*OO];
__device__ __nv_bfloat16 g_Wo2H[OO*HH], g_Wo2L[OO*HH];

__device__ __forceinline__ unsigned ld_acq(const unsigned* p) {
    unsigned v;
    asm volatile("ld.acquire.gpu.global.u32 %0, [%1];" : "=r"(v) : "l"(p));
    return v;
}
__device__ __forceinline__ void red_rel(unsigned* p, unsigned v) {
    asm volatile("red.add.release.gpu.global.u32 [%0], %1;" :: "l"(p), "r"(v));
}
__device__ __forceinline__ float retanh(float x) {
    float xm = fmaxf(x, 0.0f);
    float e;
    asm("ex2.approx.f32 %0, %1;" : "=f"(e) : "f"(xm * -2.885390082f));
    return __fdividef(1.0f - e, 1.0f + e);
}
__device__ __forceinline__ uint32_t smem_u32(const void* p) {
    uint32_t a;
    asm("{ .reg .u64 t; cvta.to.shared.u64 t, %1; cvt.u32.u64 %0, t; }"
        : "=r"(a) : "l"(p));
    return a;
}
__device__ __forceinline__ void ldmx4(uint32_t* r, uint32_t addr) {
    asm volatile("ldmatrix.sync.aligned.m8n8.x4.shared.b16 {%0,%1,%2,%3}, [%4];"
                 : "=r"(r[0]), "=r"(r[1]), "=r"(r[2]), "=r"(r[3]) : "r"(addr));
}
__device__ __forceinline__ void mma16816(float* c, const uint32_t* a,
                                         uint32_t b0, uint32_t b1) {
    asm volatile(
        "mma.sync.aligned.m16n8k16.row.col.f32.bf16.bf16.f32 "
        "{%0,%1,%2,%3}, {%4,%5,%6,%7}, {%8,%9}, {%0,%1,%2,%3};"
        : "+f"(c[0]), "+f"(c[1]), "+f"(c[2]), "+f"(c[3])
        : "r"(a[0]), "r"(a[1]), "r"(a[2]), "r"(a[3]), "r"(b0), "r"(b1));
}
__device__ __forceinline__ void cpa16(uint32_t dst, const void* src) {
    asm volatile("cp.async.cg.shared.global [%0], [%1], 16;"
                 :: "r"(dst), "l"(src) : "memory");
}
#define CPA_COMMIT asm volatile("cp.async.commit_group;" ::: "memory")
#define CPA_WAIT1  asm volatile("cp.async.wait_group 1;" ::: "memory")
#define CPA_WAIT0  asm volatile("cp.async.wait_group 0;" ::: "memory")

// ======================= HMMA GEMM (R13-proven, 256 thr) ======================
__global__ __launch_bounds__(256, 2) void hgemm(
    const __nv_bfloat16* __restrict__ Ahi, const __nv_bfloat16* __restrict__ Alo,
    const __nv_bfloat16* __restrict__ Bhi, const __nv_bfloat16* __restrict__ Blo,
    const float* __restrict__ b1, const float* __restrict__ b2,
    float* __restrict__ C, __nv_bfloat16* __restrict__ hiO,
    __nv_bfloat16* __restrict__ loO,
    int K, int Nc, int D1, int D2, int act, int omode)
{
    __shared__ __align__(16) __nv_bfloat16 smA[2][128 * 40];
    __shared__ __align__(16) __nv_bfloat16 smB[2][128 * 40];

    const int tid = threadIdx.x, lane = tid & 31, wid = tid >> 5;
    const int m0 = blockIdx.y * 128, j0 = blockIdx.x * 128;
    const int wm = wid & 3, wn = wid >> 2;
    const int lrow = tid >> 1, lhalf = tid & 1;
    const int KC = K / 32, NCH = 3 * KC;

    float acc[2][8][4];
#pragma unroll
    for (int i = 0; i < 2; i++)
#pragma unroll
        for (int j = 0; j < 8; j++)
#pragma unroll
            for (int q = 0; q < 4; q++) acc[i][j][q] = 0.0f;

    auto copy_chunk = [&](int c, int b) {
        const int p = c / KC;
        const int kt = (c - p * KC) * 32;
        const __nv_bfloat16* pA = (p == 2) ? Alo : Ahi;
        const __nv_bfloat16* pB = (p == 1) ? Blo : Bhi;
        const uint32_t da = smem_u32(&smA[b][lrow * 40 + lhalf * 16]);
        const __nv_bfloat16* ga = pA + (size_t)(m0 + lrow) * K + kt + lhalf * 16;
        cpa16(da, ga); cpa16(da + 16, ga + 8);
        const uint32_t db = smem_u32(&smB[b][lrow * 40 + lhalf * 16]);
        const __nv_bfloat16* gb = pB + (size_t)(j0 + lrow) * K + kt + lhalf * 16;
        cpa16(db, gb); cpa16(db + 16, gb + 8);
    };

    copy_chunk(0, 0); CPA_COMMIT;
    copy_chunk(1, 1); CPA_COMMIT;

    for (int c = 0; c < NCH; c++) {
        if (c + 1 < NCH) { CPA_WAIT1; } else { CPA_WAIT0; }
        __syncthreads();
        const int cur = c & 1;
        const uint32_t baseA = smem_u32(&smA[cur][0]);
        const uint32_t baseB = smem_u32(&smB[cur][0]);
#pragma unroll
        for (int kk = 0; kk < 2; kk++) {
            uint32_t aF[2][4], bF[4][4];
#pragma unroll
            for (int mt = 0; mt < 2; mt++)
                ldmx4(aF[mt], baseA +
                      ((wm * 32 + mt * 16 + (lane & 15)) * 40 + kk * 16 + (lane >> 4) * 8) * 2);
#pragma unroll
            for (int np = 0; np < 4; np++)
                ldmx4(bF[np], baseB +
                      ((wn * 64 + np * 16 + (lane & 15)) * 40 + kk * 16 + (lane >> 4) * 8) * 2);
#pragma unroll
            for (int mt = 0; mt < 2; mt++)
#pragma unroll
                for (int np = 0; np < 4; np++) {
                    mma16816(acc[mt][2 * np + 0], aF[mt], bF[np][0], bF[np][2]);
                    mma16816(acc[mt][2 * np + 1], aF[mt], bF[np][1], bF[np][3]);
                }
        }
        __syncthreads();
        if (c + 2 < NCH) { copy_chunk(c + 2, cur); CPA_COMMIT; }
    }

#pragma unroll
    for (int mt = 0; mt < 2; mt++) {
        const int rbase = m0 + wm * 32 + mt * 16 + (lane >> 2);
#pragma unroll
        for (int half = 0; half < 2; half++) {
            const int rm = rbase + half * 8;
            const int orow = (rm % D1) * D2 + rm / D1;
#pragma unroll
            for (int nt = 0; nt < 8; nt++) {
                const int cn = j0 + wn * 64 + nt * 8 + (lane & 3) * 2;
                float bb0 = b1[cn], bb1 = b1[cn + 1];
                if (b2) { bb0 += b2[cn]; bb1 += b2[cn + 1]; }
                float x = acc[mt][nt][2 * half + 0] + bb0;
                float y = acc[mt][nt][2 * half + 1] + bb1;
                if (act) { x = retanh(x); y = retanh(y); }
                const size_t oidx = (size_t)orow * Nc + cn;
                if (omode == 0) {
                    float2 v; v.x = x; v.y = y;
                    *(float2*)(C + oidx) = v;
                } else {
                    __nv_bfloat16 hx = __float2bfloat16(x);
                    __nv_bfloat16 hy = __float2bfloat16(y);
                    __nv_bfloat16 lx = __float2bfloat16(x - __bfloat162float(hx));
                    __nv_bfloat16 ly = __float2bfloat16(y - __bfloat162float(hy));
                    *(__nv_bfloat162*)(hiO + oidx) = __nv_bfloat162(hx, hy);
                    *(__nv_bfloat162*)(loO + oidx) = __nv_bfloat162(lx, ly);
                }
            }
        }
    }
}

// ======================= fp32 -> bf16 hi/lo split ==============================
__global__ __launch_bounds__(256) void cvt_split(
    const float* __restrict__ x, __nv_bfloat16* __restrict__ hi,
    __nv_bfloat16* __restrict__ lo, int n4)
{
    const int i = blockIdx.x * 256 + threadIdx.x;
    if (i >= n4) return;
    const float4 v = ((const float4*)x)[i];
    __nv_bfloat16 h0 = __float2bfloat16(v.x), h1 = __float2bfloat16(v.y);
    __nv_bfloat16 h2 = __float2bfloat16(v.z), h3 = __float2bfloat16(v.w);
    __nv_bfloat16 l0 = __float2bfloat16(v.x - __bfloat162float(h0));
    __nv_bfloat16 l1 = __float2bfloat16(v.y - __bfloat162float(h1));
    __nv_bfloat16 l2 = __float2bfloat16(v.z - __bfloat162float(h2));
    __nv_bfloat16 l3 = __float2bfloat16(v.w - __bfloat162float(h3));
    ((__nv_bfloat162*)hi)[2 * i]     = __nv_bfloat162(h0, h1);
    ((__nv_bfloat162*)hi)[2 * i + 1] = __nv_bfloat162(h2, h3);
    ((__nv_bfloat162*)lo)[2 * i]     = __nv_bfloat162(l0, l1);
    ((__nv_bfloat162*)lo)[2 * i + 1] = __nv_bfloat162(l2, l3);
}
__global__ __launch_bounds__(1024) void reset_flags_kernel() {
    g_gflag[threadIdx.x] = 0u;
}

// ======================= HMMA persistent recurrence ===========================
// 128 CTAs = 2 halves x 64 c-slices of 16. Warp w owns k-chunk [64w,64w+64).
// Per step: h tile (32n x 64k, bf16 hi/lo) via cp.async -> 3-pass HMMA vs Wh
// slice (SMEM, hi/lo) -> fragment-indexed 16-warp SMEM reduce -> retanh ->
// publish bf16 hi/lo into g_aHi/g_aLo ([t][n][H] - doubles as h exchange AND
// downstream GEMM input). SMEM: Wh 72KB + h tiles 144KB (redU aliases h).
#define RGRID 128
#define RTHR  512
#define RSMEM 221184

__global__ __launch_bounds__(RTHR) void recur_kernel(
    const float* __restrict__ buf, const float* __restrict__ Wh,
    const __nv_bfloat16* __restrict__ h0H, const __nv_bfloat16* __restrict__ h0L,
    __nv_bfloat16* __restrict__ aHp, __nv_bfloat16* __restrict__ aLp)
{
    extern __shared__ char sm[];
    const int tid = threadIdx.x, lane = tid & 31, wid = tid >> 5;
    const int bidb = blockIdx.x >> 6, bidh = blockIdx.x & 63;
    const int nb0 = bidb * 32, c0 = bidh * 16, k0 = wid * 64;

    // SMEM byte offsets: Wh hi/lo per warp (rows=c, 144B stride), h tiles per
    // warp (rows=n, 144B stride), redU aliases the h region (h dead post-MMA).
    const int whHoff = wid * 4608, whLoff = whHoff + 2304;
    const int hHoff  = 73728 + wid * 9216, hLoff = hHoff + 4608;
    float* redF = (float*)(sm + 73728);

    // Wh slice -> SMEM bf16 hi/lo (once)
#pragma unroll
    for (int idx = 0; idx < 32; idx++) {
        const int c = idx >> 1, k = ((idx & 1) << 5) + lane;
        const float v = Wh[(size_t)(c0 + c) * HH + k0 + k];
        __nv_bfloat16 h = __float2bfloat16(v);
        *(__nv_bfloat16*)(sm + whHoff + c * 144 + k * 2) = h;
        *(__nv_bfloat16*)(sm + whLoff + c * 144 + k * 2) =
            __float2bfloat16(v - __bfloat162float(h));
    }
    __syncthreads();

    const int cR = lane & 15, nR = 2 * wid + (lane >> 4);
    // gather indices: output (nR, cR) -> (srcLane, frag) in producer fragments
    const int n16 = nR & 15;
    const int srcLane = ((n16 & 7) << 2) | ((cR >> 1) & 3);
    const int frag = (nR >> 4) * 8 + (cR >> 3) * 4 + ((n16 >> 3) << 1) + (cR & 1);

    const unsigned* wf = &g_gflag[(bidb * 16 + wid) * 32];
    unsigned* pf = &g_gflag[(bidb * 16 + (bidh >> 2)) * 32];
    const uint32_t hHs = smem_u32(sm + hHoff), hLs = smem_u32(sm + hLoff);
    const uint32_t whHs = smem_u32(sm + whHoff), whLs = smem_u32(sm + whLoff);

    for (int t = 0; t < TT; t++) {
        const size_t oidx = (size_t)t * NHh + (size_t)(nb0 + nR) * HH + (c0 + cR);
        const float x_pre = __ldcg(buf + oidx);
        {
            const unsigned tgt = 4u * (unsigned)t;
            while (ld_acq(wf) < tgt) __nanosleep(20);
        }
        // load this warp's h tile (lane = n row, 128B of k)
        const __nv_bfloat16* srcH =
            (t ? aHp + (size_t)(t - 1) * NHh : h0H) + (size_t)(nb0 + lane) * HH + k0;
        const __nv_bfloat16* srcL =
            (t ? aLp + (size_t)(t - 1) * NHh : h0L) + (size_t)(nb0 + lane) * HH + k0;
#pragma unroll
        for (int j = 0; j < 8; j++) {
            cpa16(hHs + lane * 144 + j * 16, srcH + j * 8);
            cpa16(hLs + lane * 144 + j * 16, srcL + j * 8);
        }
        CPA_COMMIT; CPA_WAIT0;
        __syncthreads();   // S1: h visible CTA-wide; prior redU reads done

        float acc[2][2][4];
#pragma unroll
        for (int a = 0; a < 2; a++)
#pragma unroll
            for (int b = 0; b < 2; b++)
#pragma unroll
                for (int q = 0; q < 4; q++) acc[a][b][q] = 0.0f;

#pragma unroll
        for (int p = 0; p < 3; p++) {
            const uint32_t ab = (p == 2) ? hLs : hHs;
            const uint32_t bb = (p == 1) ? whLs : whHs;
#pragma unroll
            for (int kk = 0; kk < 4; kk++) {
                uint32_t aF0[4], aF1[4], bF[4];
                ldmx4(aF0, ab + (((lane & 15)) * 72 + kk * 16 + (lane >> 4) * 8) * 2);
                ldmx4(aF1, ab + ((16 + (lane & 15)) * 72 + kk * 16 + (lane >> 4) * 8) * 2);
                ldmx4(bF,  bb + (((lane & 15)) * 72 + kk * 16 + (lane >> 4) * 8) * 2);
                mma16816(acc[0][0], aF0, bF[0], bF[2]);
                mma16816(acc[0][1], aF0, bF[1], bF[3]);
                mma16816(acc[1][0], aF1, bF[0], bF[2]);
                mma16816(acc[1][1], aF1, bF[1], bF[3]);
            }
        }
        __syncthreads();   // S2: all MMA h-reads done (redU clobbers h region)

        {
            float* rp = &redF[(size_t)(wid * 32 + lane) * 17];
#pragma unroll
            for (int mt = 0; mt < 2; mt++)
#pragma unroll
                for (int nt = 0; nt < 2; nt++)
#pragma unroll
                    for (int q = 0; q < 4; q++)
                        rp[mt * 8 + nt * 4 + q] = acc[mt][nt][q];
        }
        __syncthreads();   // S3

        float s = 0.0f;
#pragma unroll
        for (int w = 0; w < 16; w++) s += redF[(w * 32 + srcLane) * 17 + frag];
        const float v = retanh(s + x_pre);
        __nv_bfloat16 hv = __float2bfloat16(v);
        aHp[oidx] = hv;
        aLp[oidx] = __float2bfloat16(v - __bfloat162float(hv));
        __syncthreads();   // S4: redU reads done; publishes before flag
        if (tid == 0) red_rel(pf, 1u);
    }
}

// ======================= launcher ==============================================
static void cvt(const float* x, __nv_bfloat16* hi, __nv_bfloat16* lo, int n) {
    cvt_split<<<(n / 4 + 255) / 256, 256>>>(x, hi, lo, n / 4);
}

extern "C" void kernel_launch(void* const* d_in, const int* in_sizes, int n_in,
                              void* d_out, int out_size)
{
    const float* data = (const float*)d_in[0];
    const float* h0_v = (const float*)d_in[1];
    const float* h0_m = (const float*)d_in[2];
    const float* Wi   = (const float*)d_in[3];
    const float* bi   = (const float*)d_in[4];
    const float* Wh   = (const float*)d_in[5];
    const float* bh   = (const float*)d_in[6];
    const float* Wo   = (const float*)d_in[7];
    const float* bo   = (const float*)d_in[8];
    const float* Wt   = (const float*)d_in[9];
    const float* bt   = (const float*)d_in[10];
    const float* Wi2  = (const float*)d_in[11];
    const float* bi2  = (const float*)d_in[12];
    const float* Wh2  = (const float*)d_in[13];
    const float* bh2  = (const float*)d_in[14];
    const float* Wo2  = (const float*)d_in[15];
    const float* bo2  = (const float*)d_in[16];
    float* out = (float*)d_out;

    float *bufA, *bufB;
    cudaGetSymbolAddress((void**)&bufA, g_bufA);
    cudaGetSymbolAddress((void**)&bufB, g_bufB);
    __nv_bfloat16 *h0H,*h0L,*dH,*dL,*aH,*aL,*oH,*oL,*o2H,*o2L;
    __nv_bfloat16 *WiH,*WiL,*WoH,*WoL,*WtH,*WtL,*Wi2H,*Wi2L,*Wo2H,*Wo2L;
    cudaGetSymbolAddress((void**)&h0H, g_h0H);  cudaGetSymbolAddress((void**)&h0L, g_h0L);
    cudaGetSymbolAddress((void**)&dH, g_dHi);   cudaGetSymbolAddress((void**)&dL, g_dLo);
    cudaGetSymbolAddress((void**)&aH, g_aHi);   cudaGetSymbolAddress((void**)&aL, g_aLo);
    cudaGetSymbolAddress((void**)&oH, g_oHi);   cudaGetSymbolAddress((void**)&oL, g_oLo);
    cudaGetSymbolAddress((void**)&o2H, g_o2Hi); cudaGetSymbolAddress((void**)&o2L, g_o2Lo);
    cudaGetSymbolAddress((void**)&WiH, g_WiH);  cudaGetSymbolAddress((void**)&WiL, g_WiL);
    cudaGetSymbolAddress((void**)&WoH, g_WoH);  cudaGetSymbolAddress((void**)&WoL, g_WoL);
    cudaGetSymbolAddress((void**)&WtH, g_WtH);  cudaGetSymbolAddress((void**)&WtL, g_WtL);
    cudaGetSymbolAddress((void**)&Wi2H, g_Wi2H); cudaGetSymbolAddress((void**)&Wi2L, g_Wi2L);
    cudaGetSymbolAddress((void**)&Wo2H, g_Wo2H); cudaGetSymbolAddress((void**)&Wo2L, g_Wo2L);

    cudaFuncSetAttribute(recur_kernel,
                         cudaFuncAttributeMaxDynamicSharedMemorySize, RSMEM);

    cvt(Wi,  WiH,  WiL,  HH * II);
    cvt(Wo,  WoH,  WoL,  OO * HH);
    cvt(Wt,  WtH,  WtL,  OO * OO);
    cvt(Wi2, Wi2H, Wi2L, HH * OO);
    cvt(Wo2, Wo2H, Wo2L, OO * HH);
    cvt(data, dH, dL, NT * II);

    // G1: inp_v = data @ Wi^T + (bi+bh) -> fp32 [T,N,H]
    hgemm<<<dim3(HH / 128, NT / 128), 256>>>(
        dH, dL, WiH, WiL, bi, bh, bufA, nullptr, nullptr, II, HH, TT, NB, 0, 0);
    // visual recurrence (HMMA; hs_v -> aH/aL)
    cvt(h0_v, h0H, h0L, NB * HH);
    reset_flags_kernel<<<1, 1024>>>();
    recur_kernel<<<RGRID, RTHR, RSMEM>>>(bufA, Wh, h0H, h0L, aH, aL);
    // G3: out_v = hs_v @ Wo^T + bo -> bf16 split [N,T,O]
    hgemm<<<dim3(OO / 128, NT / 128), 256>>>(
        aH, aL, WoH, WoL, bo, nullptr, nullptr, oH, oL, HH, OO, NB, TT, 0, 1);
    // G4: out_t = retanh(out_v @ Wt^T + bt) -> bf16 split [N,T,O]
    hgemm<<<dim3(OO / 128, NT / 128), 256>>>(
        oH, oL, WtH, WtL, bt, nullptr, nullptr, o2H, o2L, OO, OO, NT, 1, 1, 1);
    // G5: inp_m = out_t @ Wi2^T + (bi2+bh2) -> fp32 [T,N,H]
    hgemm<<<dim3(HH / 128, NT / 128), 256>>>(
        o2H, o2L, Wi2H, Wi2L, bi2, bh2, bufB, nullptr, nullptr, OO, HH, TT, NB, 0, 0);
    // motor recurrence (HMMA; hs_m -> aH/aL)
    cvt(h0_m, h0H, h0L, NB * HH);
    reset_flags_kernel<<<1, 1024>>>();
    recur_kernel<<<RGRID, RTHR, RSMEM>>>(bufB, Wh2, h0H, h0L, aH, aL);
    // G7: out_m = hs_m @ Wo2^T + bo2 -> fp32 [N,T,O]
    hgemm<<<dim3(OO / 128, NT / 128), 256>>>(
        aH, aL, Wo2H, Wo2L, bo2, nullptr, out, nullptr, nullptr, HH, OO, NB, TT, 0, 0);
}

// round 17
// speedup vs baseline: 2.3444x; 1.5993x over previous
#include <cuda_runtime.h>
#include <cuda_bf16.h>
#include <cstdint>

#define NB 64
#define TT 512
#define II 512
#define HH 1024
#define OO 512
#define NT (NB*TT)
#define NHh (NB*HH)

__device__ float g_bufA[TT*NB*HH];
__device__ float g_bufB[TT*NB*HH];
__device__ unsigned g_gflag[32*32];
// h exchange: [block16][n64][k64] bf16, ping-pong, hi/lo
__device__ __nv_bfloat16 g_hxH[2][16*64*64], g_hxL[2][16*64*64];
__device__ __nv_bfloat16 g_dHi[NT*II],  g_dLo[NT*II];
__device__ __nv_bfloat16 g_aHi[NT*HH],  g_aLo[NT*HH];
__device__ __nv_bfloat16 g_oHi[NT*OO],  g_oLo[NT*OO];
__device__ __nv_bfloat16 g_o2Hi[NT*OO], g_o2Lo[NT*OO];
__device__ __nv_bfloat16 g_WiH[HH*II],  g_WiL[HH*II];
__device__ __nv_bfloat16 g_WoH[OO*HH],  g_WoL[OO*HH];
__device__ __nv_bfloat16 g_WtH[OO*OO],  g_WtL[OO*OO];
__device__ __nv_bfloat16 g_Wi2H[HH*OO], g_Wi2L[HH*OO];
__device__ __nv_bfloat16 g_Wo2H[OO*HH], g_Wo2L[OO*HH];

__device__ __forceinline__ unsigned ld_acq(const unsigned* p) {
    unsigned v;
    asm volatile("ld.acquire.gpu.global.u32 %0, [%1];" : "=r"(v) : "l"(p));
    return v;
}
__device__ __forceinline__ void red_rel(unsigned* p, unsigned v) {
    asm volatile("red.add.release.gpu.global.u32 [%0], %1;" :: "l"(p), "r"(v));
}
__device__ __forceinline__ float retanh(float x) {
    float xm = fmaxf(x, 0.0f);
    float e;
    asm("ex2.approx.f32 %0, %1;" : "=f"(e) : "f"(xm * -2.885390082f));
    return __fdividef(1.0f - e, 1.0f + e);
}
__device__ __forceinline__ uint32_t smem_u32(const void* p) {
    uint32_t a;
    asm("{ .reg .u64 t; cvta.to.shared.u64 t, %1; cvt.u32.u64 %0, t; }"
        : "=r"(a) : "l"(p));
    return a;
}
__device__ __forceinline__ void ldmx4(uint32_t* r, uint32_t addr) {
    asm volatile("ldmatrix.sync.aligned.m8n8.x4.shared.b16 {%0,%1,%2,%3}, [%4];"
                 : "=r"(r[0]), "=r"(r[1]), "=r"(r[2]), "=r"(r[3]) : "r"(addr));
}
__device__ __forceinline__ void mma16816(float* c, const uint32_t* a,
                                         uint32_t b0, uint32_t b1) {
    asm volatile(
        "mma.sync.aligned.m16n8k16.row.col.f32.bf16.bf16.f32 "
        "{%0,%1,%2,%3}, {%4,%5,%6,%7}, {%8,%9}, {%0,%1,%2,%3};"
        : "+f"(c[0]), "+f"(c[1]), "+f"(c[2]), "+f"(c[3])
        : "r"(a[0]), "r"(a[1]), "r"(a[2]), "r"(a[3]), "r"(b0), "r"(b1));
}
__device__ __forceinline__ void cpa16(uint32_t dst, const void* src) {
    asm volatile("cp.async.cg.shared.global [%0], [%1], 16;"
                 :: "r"(dst), "l"(src) : "memory");
}
#define CPA_COMMIT asm volatile("cp.async.commit_group;" ::: "memory")
#define CPA_WAIT1  asm volatile("cp.async.wait_group 1;" ::: "memory")
#define CPA_WAIT0  asm volatile("cp.async.wait_group 0;" ::: "memory")

// ======================= HMMA GEMM (R13-proven, 256 thr) ======================
__global__ __launch_bounds__(256, 2) void hgemm(
    const __nv_bfloat16* __restrict__ Ahi, const __nv_bfloat16* __restrict__ Alo,
    const __nv_bfloat16* __restrict__ Bhi, const __nv_bfloat16* __restrict__ Blo,
    const float* __restrict__ b1, const float* __restrict__ b2,
    float* __restrict__ C, __nv_bfloat16* __restrict__ hiO,
    __nv_bfloat16* __restrict__ loO,
    int K, int Nc, int D1, int D2, int act, int omode)
{
    __shared__ __align__(16) __nv_bfloat16 smA[2][128 * 40];
    __shared__ __align__(16) __nv_bfloat16 smB[2][128 * 40];

    const int tid = threadIdx.x, lane = tid & 31, wid = tid >> 5;
    const int m0 = blockIdx.y * 128, j0 = blockIdx.x * 128;
    const int wm = wid & 3, wn = wid >> 2;
    const int lrow = tid >> 1, lhalf = tid & 1;
    const int KC = K / 32, NCH = 3 * KC;

    float acc[2][8][4];
#pragma unroll
    for (int i = 0; i < 2; i++)
#pragma unroll
        for (int j = 0; j < 8; j++)
#pragma unroll
            for (int q = 0; q < 4; q++) acc[i][j][q] = 0.0f;

    auto copy_chunk = [&](int c, int b) {
        const int p = c / KC;
        const int kt = (c - p * KC) * 32;
        const __nv_bfloat16* pA = (p == 2) ? Alo : Ahi;
        const __nv_bfloat16* pB = (p == 1) ? Blo : Bhi;
        const uint32_t da = smem_u32(&smA[b][lrow * 40 + lhalf * 16]);
        const __nv_bfloat16* ga = pA + (size_t)(m0 + lrow) * K + kt + lhalf * 16;
        cpa16(da, ga); cpa16(da + 16, ga + 8);
        const uint32_t db = smem_u32(&smB[b][lrow * 40 + lhalf * 16]);
        const __nv_bfloat16* gb = pB + (size_t)(j0 + lrow) * K + kt + lhalf * 16;
        cpa16(db, gb); cpa16(db + 16, gb + 8);
    };

    copy_chunk(0, 0); CPA_COMMIT;
    copy_chunk(1, 1); CPA_COMMIT;

    for (int c = 0; c < NCH; c++) {
        if (c + 1 < NCH) { CPA_WAIT1; } else { CPA_WAIT0; }
        __syncthreads();
        const int cur = c & 1;
        const uint32_t baseA = smem_u32(&smA[cur][0]);
        const uint32_t baseB = smem_u32(&smB[cur][0]);
#pragma unroll
        for (int kk = 0; kk < 2; kk++) {
            uint32_t aF[2][4], bF[4][4];
#pragma unroll
            for (int mt = 0; mt < 2; mt++)
                ldmx4(aF[mt], baseA +
                      ((wm * 32 + mt * 16 + (lane & 15)) * 40 + kk * 16 + (lane >> 4) * 8) * 2);
#pragma unroll
            for (int np = 0; np < 4; np++)
                ldmx4(bF[np], baseB +
                      ((wn * 64 + np * 16 + (lane & 15)) * 40 + kk * 16 + (lane >> 4) * 8) * 2);
#pragma unroll
            for (int mt = 0; mt < 2; mt++)
#pragma unroll
                for (int np = 0; np < 4; np++) {
                    mma16816(acc[mt][2 * np + 0], aF[mt], bF[np][0], bF[np][2]);
                    mma16816(acc[mt][2 * np + 1], aF[mt], bF[np][1], bF[np][3]);
                }
        }
        __syncthreads();
        if (c + 2 < NCH) { copy_chunk(c + 2, cur); CPA_COMMIT; }
    }

#pragma unroll
    for (int mt = 0; mt < 2; mt++) {
        const int rbase = m0 + wm * 32 + mt * 16 + (lane >> 2);
#pragma unroll
        for (int half = 0; half < 2; half++) {
            const int rm = rbase + half * 8;
            const int orow = (rm % D1) * D2 + rm / D1;
#pragma unroll
            for (int nt = 0; nt < 8; nt++) {
                const int cn = j0 + wn * 64 + nt * 8 + (lane & 3) * 2;
                float bb0 = b1[cn], bb1 = b1[cn + 1];
                if (b2) { bb0 += b2[cn]; bb1 += b2[cn + 1]; }
                float x = acc[mt][nt][2 * half + 0] + bb0;
                float y = acc[mt][nt][2 * half + 1] + bb1;
                if (act) { x = retanh(x); y = retanh(y); }
                const size_t oidx = (size_t)orow * Nc + cn;
                if (omode == 0) {
                    float2 v; v.x = x; v.y = y;
                    *(float2*)(C + oidx) = v;
                } else {
                    __nv_bfloat16 hx = __float2bfloat16(x);
                    __nv_bfloat16 hy = __float2bfloat16(y);
                    __nv_bfloat16 lx = __float2bfloat16(x - __bfloat162float(hx));
                    __nv_bfloat16 ly = __float2bfloat16(y - __bfloat162float(hy));
                    *(__nv_bfloat162*)(hiO + oidx) = __nv_bfloat162(hx, hy);
                    *(__nv_bfloat162*)(loO + oidx) = __nv_bfloat162(lx, ly);
                }
            }
        }
    }
}

// ======================= converts + helpers ===================================
__global__ __launch_bounds__(256) void cvt_split(
    const float* __restrict__ x, __nv_bfloat16* __restrict__ hi,
    __nv_bfloat16* __restrict__ lo, int n4)
{
    const int i = blockIdx.x * 256 + threadIdx.x;
    if (i >= n4) return;
    const float4 v = ((const float4*)x)[i];
    __nv_bfloat16 h0 = __float2bfloat16(v.x), h1 = __float2bfloat16(v.y);
    __nv_bfloat16 h2 = __float2bfloat16(v.z), h3 = __float2bfloat16(v.w);
    __nv_bfloat16 l0 = __float2bfloat16(v.x - __bfloat162float(h0));
    __nv_bfloat16 l1 = __float2bfloat16(v.y - __bfloat162float(h1));
    __nv_bfloat16 l2 = __float2bfloat16(v.z - __bfloat162float(h2));
    __nv_bfloat16 l3 = __float2bfloat16(v.w - __bfloat162float(h3));
    ((__nv_bfloat162*)hi)[2 * i]     = __nv_bfloat162(h0, h1);
    ((__nv_bfloat162*)hi)[2 * i + 1] = __nv_bfloat162(h2, h3);
    ((__nv_bfloat162*)lo)[2 * i]     = __nv_bfloat162(l0, l1);
    ((__nv_bfloat162*)lo)[2 * i + 1] = __nv_bfloat162(l2, l3);
}
// h0 [N,H] fp32 -> hx[0] block layout bf16 hi/lo
__global__ __launch_bounds__(512) void h0_prep(const float* __restrict__ h0) {
    const int idx = blockIdx.x * 512 + threadIdx.x;      // 0..65535
    const int w = idx >> 12, n = (idx >> 6) & 63, kk = idx & 63;
    const float v = h0[(size_t)n * HH + w * 64 + kk];
    __nv_bfloat16 h = __float2bfloat16(v);
    g_hxH[0][idx] = h;
    g_hxL[0][idx] = __float2bfloat16(v - __bfloat162float(h));
}
__global__ __launch_bounds__(1024) void reset_flags_kernel() {
    g_gflag[threadIdx.x] = 0u;
}

// ======================= HMMA persistent recurrence (block exchange) ==========
// 128 CTAs = 2 halves x 64 c-slices. Warp w owns k-chunk [64w,64w+64).
// A = Wh slice [c16][k] SMEM (non-trans), B = h [n32][k] SMEM (non-trans).
// h exchanged via [block16][n64][k64] gmem blocks (coalesced cp.async).
#define RGRID 128
#define RTHR  512
#define RSMEM (73728 + 147456)   // Wh 72KB + h tiles (redU aliased) 144KB

__global__ __launch_bounds__(RTHR) void recur_kernel(
    const float* __restrict__ buf, const float* __restrict__ Wh,
    __nv_bfloat16* __restrict__ aHp, __nv_bfloat16* __restrict__ aLp)
{
    extern __shared__ char sm[];
    const int tid = threadIdx.x, lane = tid & 31, wid = tid >> 5;
    const int bidb = blockIdx.x >> 6, bidh = blockIdx.x & 63;
    const int nb0 = bidb * 32, c0 = bidh * 16, k0 = wid * 64;

    const int whHoff = wid * 4608, whLoff = whHoff + 2304;   // [c16][144B]
    const int hoff   = 73728 + wid * 9216;                    // hi [n32][144B]
    const int hLoffB = hoff + 4608;                           // lo
    float* redF = (float*)(sm + 73728);                       // warp regions

    // Wh slice -> SMEM bf16 hi/lo (rows = c, 144B stride)
    for (int idx = lane; idx < 1024; idx += 32) {
        const int c = idx >> 6, k = idx & 63;
        const float v = Wh[(size_t)(c0 + c) * HH + k0 + k];
        __nv_bfloat16 h = __float2bfloat16(v);
        *(__nv_bfloat16*)(sm + whHoff + c * 144 + k * 2) = h;
        *(__nv_bfloat16*)(sm + whLoff + c * 144 + k * 2) =
            __float2bfloat16(v - __bfloat162float(h));
    }
    __syncthreads();

    const int cR = lane & 15, nR = 2 * wid + (lane >> 4);
    const int srcLane = ((cR & 7) << 2) | (wid & 3);
    const int frag = ((nR >> 3) & 3) * 4 + (cR >> 3) * 2 + (nR & 1);

    const unsigned* wf = &g_gflag[(bidb * 16 + wid) * 32];
    unsigned* pf = &g_gflag[(bidb * 16 + (bidh >> 2)) * 32];
    const uint32_t whHs = smem_u32(sm + whHoff), whLs = smem_u32(sm + whLoff);
    const uint32_t hHs = smem_u32(sm + hoff), hLs = smem_u32(sm + hLoffB);
    // consumer copy map: 4 rows per instr, fully coalesced
    const int crow = lane >> 3, cchk = (lane & 7) * 16;

    for (int t = 0; t < TT; t++) {
        const size_t oidx = (size_t)t * NHh + (size_t)(nb0 + nR) * HH + (c0 + cR);
        const float x_pre = __ldcg(buf + oidx);
        {
            const unsigned tgt = 4u * (unsigned)t;
            while (ld_acq(wf) < tgt) __nanosleep(20);
        }
        // load h block slice: rows nb0..nb0+31 of block wid (dense 128B rows)
        {
            const __nv_bfloat16* sH = g_hxH[t & 1] + ((wid * 64 + nb0) << 6);
            const __nv_bfloat16* sL = g_hxL[t & 1] + ((wid * 64 + nb0) << 6);
#pragma unroll
            for (int i = 0; i < 8; i++) {
                const int r = 4 * i + crow;
                cpa16(hHs + r * 144 + cchk, sH + r * 64 + (cchk >> 1));
                cpa16(hLs + r * 144 + cchk, sL + r * 64 + (cchk >> 1));
            }
        }
        CPA_COMMIT; CPA_WAIT0;
        __syncwarp();

        float acc[4][4];
#pragma unroll
        for (int j = 0; j < 4; j++)
#pragma unroll
            for (int q = 0; q < 4; q++) acc[j][q] = 0.0f;

#pragma unroll
        for (int p = 0; p < 3; p++) {
            const uint32_t ab = (p == 1) ? whLs : whHs;   // A = Wh
            const uint32_t bb = (p == 2) ? hLs : hHs;     // B = h
#pragma unroll
            for (int kk = 0; kk < 4; kk++) {
                uint32_t aF[4], bF[2][4];
                ldmx4(aF, ab + (lane & 15) * 144 + kk * 32 + (lane >> 4) * 16);
#pragma unroll
                for (int nt = 0; nt < 2; nt++)
                    ldmx4(bF[nt], bb + (nt * 16 + (lane & 15)) * 144
                                     + kk * 32 + (lane >> 4) * 16);
#pragma unroll
                for (int nt = 0; nt < 2; nt++) {
                    mma16816(acc[nt * 2 + 0], aF, bF[nt][0], bF[nt][2]);
                    mma16816(acc[nt * 2 + 1], aF, bF[nt][1], bF[nt][3]);
                }
            }
        }

        // partials -> own warp's region (aliases own h tile; warp-local WAR ok)
        {
            float* rp = redF + wid * 2304 + lane * 17;
#pragma unroll
            for (int nf = 0; nf < 4; nf++)
#pragma unroll
                for (int q = 0; q < 4; q++) rp[nf * 4 + q] = acc[nf][q];
        }
        __syncthreads();   // A

        float s = 0.0f;
#pragma unroll
        for (int w = 0; w < 16; w++)
            s += redF[w * 2304 + srcLane * 17 + frag];
        const float v = retanh(s + x_pre);
        const __nv_bfloat16 hv = __float2bfloat16(v);
        const __nv_bfloat16 lv = __float2bfloat16(v - __bfloat162float(hv));
        aHp[oidx] = hv;                          // [t][n][H] for downstream GEMM
        aLp[oidx] = lv;
        {                                        // hx block publish for next step
            const int bi = ((bidh >> 2) * 64 + nb0 + nR) * 64
                         + (bidh & 3) * 16 + cR;
            g_hxH[(t + 1) & 1][bi] = hv;
            g_hxL[(t + 1) & 1][bi] = lv;
        }
        __syncthreads();   // B
        if (tid == 0) red_rel(pf, 1u);
    }
}

// ======================= launcher ==============================================
static void cvt(const float* x, __nv_bfloat16* hi, __nv_bfloat16* lo, int n) {
    cvt_split<<<(n / 4 + 255) / 256, 256>>>(x, hi, lo, n / 4);
}

extern "C" void kernel_launch(void* const* d_in, const int* in_sizes, int n_in,
                              void* d_out, int out_size)
{
    const float* data = (const float*)d_in[0];
    const float* h0_v = (const float*)d_in[1];
    const float* h0_m = (const float*)d_in[2];
    const float* Wi   = (const float*)d_in[3];
    const float* bi   = (const float*)d_in[4];
    const float* Wh   = (const float*)d_in[5];
    const float* bh   = (const float*)d_in[6];
    const float* Wo   = (const float*)d_in[7];
    const float* bo   = (const float*)d_in[8];
    const float* Wt   = (const float*)d_in[9];
    const float* bt   = (const float*)d_in[10];
    const float* Wi2  = (const float*)d_in[11];
    const float* bi2  = (const float*)d_in[12];
    const float* Wh2  = (const float*)d_in[13];
    const float* bh2  = (const float*)d_in[14];
    const float* Wo2  = (const float*)d_in[15];
    const float* bo2  = (const float*)d_in[16];
    float* out = (float*)d_out;

    float *bufA, *bufB;
    cudaGetSymbolAddress((void**)&bufA, g_bufA);
    cudaGetSymbolAddress((void**)&bufB, g_bufB);
    __nv_bfloat16 *dH,*dL,*aH,*aL,*oH,*oL,*o2H,*o2L;
    __nv_bfloat16 *WiH,*WiL,*WoH,*WoL,*WtH,*WtL,*Wi2H,*Wi2L,*Wo2H,*Wo2L;
    cudaGetSymbolAddress((void**)&dH, g_dHi);   cudaGetSymbolAddress((void**)&dL, g_dLo);
    cudaGetSymbolAddress((void**)&aH, g_aHi);   cudaGetSymbolAddress((void**)&aL, g_aLo);
    cudaGetSymbolAddress((void**)&oH, g_oHi);   cudaGetSymbolAddress((void**)&oL, g_oLo);
    cudaGetSymbolAddress((void**)&o2H, g_o2Hi); cudaGetSymbolAddress((void**)&o2L, g_o2Lo);
    cudaGetSymbolAddress((void**)&WiH, g_WiH);  cudaGetSymbolAddress((void**)&WiL, g_WiL);
    cudaGetSymbolAddress((void**)&WoH, g_WoH);  cudaGetSymbolAddress((void**)&WoL, g_WoL);
    cudaGetSymbolAddress((void**)&WtH, g_WtH);  cudaGetSymbolAddress((void**)&WtL, g_WtL);
    cudaGetSymbolAddress((void**)&Wi2H, g_Wi2H); cudaGetSymbolAddress((void**)&Wi2L, g_Wi2L);
    cudaGetSymbolAddress((void**)&Wo2H, g_Wo2H); cudaGetSymbolAddress((void**)&Wo2L, g_Wo2L);

    cudaFuncSetAttribute(recur_kernel,
                         cudaFuncAttributeMaxDynamicSharedMemorySize, RSMEM);

    cvt(Wi,  WiH,  WiL,  HH * II);
    cvt(Wo,  WoH,  WoL,  OO * HH);
    cvt(Wt,  WtH,  WtL,  OO * OO);
    cvt(Wi2, Wi2H, Wi2L, HH * OO);
    cvt(Wo2, Wo2H, Wo2L, OO * HH);
    cvt(data, dH, dL, NT * II);

    // G1: inp_v = data @ Wi^T + (bi+bh) -> fp32 [T,N,H]
    hgemm<<<dim3(HH / 128, NT / 128), 256>>>(
        dH, dL, WiH, WiL, bi, bh, bufA, nullptr, nullptr, II, HH, TT, NB, 0, 0);
    // visual recurrence (HMMA, block exchange; hs_v -> aH/aL)
    h0_prep<<<128, 512>>>(h0_v);
    reset_flags_kernel<<<1, 1024>>>();
    recur_kernel<<<RGRID, RTHR, RSMEM>>>(bufA, Wh, aH, aL);
    // G3: out_v = hs_v @ Wo^T + bo -> bf16 split [N,T,O]
    hgemm<<<dim3(OO / 128, NT / 128), 256>>>(
        aH, aL, WoH, WoL, bo, nullptr, nullptr, oH, oL, HH, OO, NB, TT, 0, 1);
    // G4: out_t = retanh(out_v @ Wt^T + bt) -> bf16 split [N,T,O]
    hgemm<<<dim3(OO / 128, NT / 128), 256>>>(
        oH, oL, WtH, WtL, bt, nullptr, nullptr, o2H, o2L, OO, OO, NT, 1, 1, 1);
    // G5: inp_m = out_t @ Wi2^T + (bi2+bh2) -> fp32 [T,N,H]
    hgemm<<<dim3(HH / 128, NT / 128), 256>>>(
        o2H, o2L, Wi2H, Wi2L, bi2, bh2, bufB, nullptr, nullptr, OO, HH, TT, NB, 0, 0);
    // motor recurrence
    h0_prep<<<128, 512>>>(h0_m);
    reset_flags_kernel<<<1, 1024>>>();
    recur_kernel<<<RGRID, RTHR, RSMEM>>>(bufB, Wh2, aH, aL);
    // G7: out_m = hs_m @ Wo2^T + bo2 -> fp32 [N,T,O]
    hgemm<<<dim3(OO / 128, NT / 128), 256>>>(
        aH, aL, Wo2H, Wo2L, bo2, nullptr, out, nullptr, nullptr, HH, OO, NB, TT, 0, 0);
}